// round 11
// baseline (speedup 1.0000x reference)
#include <cuda_runtime.h>
#include <cuda_bf16.h>
#include <stdint.h>

// Problem geometry (fixed: frames (4,8,2,4,480,640) f32)
#define Ss 8
#define Cc 8
#define Hh 480
#define Ww 640
#define HW (Hh*Ww)               // 307200
#define NPIX (32*HW)             // 9,830,400
#define MAXP 200000
#define FEAT_ELEMS (MAXP*Cc)     // 1,600,000
#define THRESH 3.0f

// One block = one 2048-pixel chunk (307200/2048 = 150 -> never crosses a frame)
#define TPB 512
#define PITER 4                  // pixels per thread (one float4 per channel)
#define CHUNK (TPB*PITER)        // 2048
#define NB (NPIX/CHUNK)          // 4800
#define NWORDS (CHUNK/32)        // 64

// Decoupled-lookback tile state: bits[1:0] flag (0=invalid,1=partial,2=inclusive),
// bits[31:2] value. Zero-initialized at module load; k_tail re-zeroes it after
// each call so the "all tiles invalid at entry" invariant holds for every replay.
__device__ unsigned g_tile[NB];
__device__ int g_total;

__device__ __forceinline__ float f4get(const float4& v, int j) {
    return j == 0 ? v.x : (j == 1 ? v.y : (j == 2 ? v.z : v.w));
}

// ---------------------------------------------------------------------------
// Kernel 1: fused mask + single-pass scan (decoupled lookback) + ranked write
// ---------------------------------------------------------------------------
__global__ void __launch_bounds__(TPB) k_fused(const float* __restrict__ frames,
                                               float* __restrict__ out) {
    const int b    = blockIdx.x;
    const int tid  = threadIdx.x;
    const int lane = tid & 31;
    const int warp = tid >> 5;

    const long chunkStart = (long)b * CHUNK;
    const int bf   = (int)(chunkStart / HW);
    const int rem0 = (int)(chunkStart % HW);
    const float* __restrict__ base = frames + (size_t)bf * Cc * HW;

    __shared__ unsigned sBits[NWORDS];
    __shared__ int sWp[NWORDS];      // per-word exclusive prefix within 32-word group
    __shared__ int sGsum[2];         // group totals (2 groups of 32 words)
    __shared__ int sWarp[TPB / 32];
    __shared__ int sExcl;

    // ---------------- Phase A: load (features stay in registers) + mask -----
    const int pix = rem0 + tid * PITER;
    float4 v[Cc];
    #pragma unroll
    for (int c = 0; c < Cc; ++c)
        v[c] = __ldg((const float4*)(base + (size_t)c * HW + pix));

    float mx = 0.f, my = 0.f, mz = 0.f, mw = 0.f;
    #pragma unroll
    for (int c = 0; c < Cc; ++c) {
        mx = fmaxf(mx, fabsf(v[c].x));
        my = fmaxf(my, fabsf(v[c].y));
        mz = fmaxf(mz, fabsf(v[c].z));
        mw = fmaxf(mw, fabsf(v[c].w));
    }
    unsigned nib = (unsigned)(mx > THRESH)
                 | ((unsigned)(my > THRESH) << 1)
                 | ((unsigned)(mz > THRESH) << 2)
                 | ((unsigned)(mw > THRESH) << 3);
    unsigned word = nib << ((lane & 7) * 4);
    word |= __shfl_xor_sync(0xffffffffu, word, 1);
    word |= __shfl_xor_sync(0xffffffffu, word, 2);
    word |= __shfl_xor_sync(0xffffffffu, word, 4);

    int myPartial = 0;
    const int wi = warp * 4 + (lane >> 3);        // my bitmap word index
    if ((lane & 7) == 0) {
        sBits[wi] = word;
        myPartial = __popc(word);
    }
    int warpSum = __reduce_add_sync(0xffffffffu, myPartial);
    if (lane == 0) sWarp[warp] = warpSum;
    __syncthreads();   // sBits + sWarp complete

    // ---------------- warp 0: publish + lookback; warps 1-2: word scan ------
    if (warp == 0) {
        int vv = (lane < TPB / 32) ? sWarp[lane] : 0;
        int cnt = __reduce_add_sync(0xffffffffu, vv);

        if (lane == 0) {
            unsigned pub = ((unsigned)cnt << 2) | (b == 0 ? 2u : 1u);
            atomicExch(&g_tile[b], pub);
        }
        int excl = 0;
        if (b > 0) {
            int idx = b - 1;
            for (;;) {
                const int my_i = idx - lane;
                unsigned t = 2u;   // out-of-range: inclusive, value 0
                if (my_i >= 0) {
                    t = *((volatile unsigned*)&g_tile[my_i]);
                    while ((t & 3u) == 0u) {
                        __nanosleep(40);
                        t = *((volatile unsigned*)&g_tile[my_i]);
                    }
                }
                unsigned ball = __ballot_sync(0xffffffffu, (t & 3u) == 2u);
                if (ball) {
                    const int L = __ffs(ball) - 1;   // closest inclusive tile
                    int contrib = (lane <= L) ? (int)(t >> 2) : 0;
                    excl += __reduce_add_sync(0xffffffffu, contrib);
                    break;
                } else {
                    excl += __reduce_add_sync(0xffffffffu, (int)(t >> 2));
                    idx -= 32;
                }
            }
        }
        if (lane == 0) {
            sExcl = excl;
            if (b > 0) atomicExch(&g_tile[b], ((unsigned)(cnt + excl) << 2) | 2u);
            if (b == NB - 1) g_total = cnt + excl;
        }
    } else if (warp <= 2) {
        // exclusive scan of the 64 word-popcounts (2 groups of 32)
        const int g = warp - 1;
        const int i = g * 32 + lane;
        int p = __popc(sBits[i]);
        int inc = p;
        #pragma unroll
        for (int o = 1; o < 32; o <<= 1) {
            int s = __shfl_up_sync(0xffffffffu, inc, o);
            if (lane >= o) inc += s;
        }
        sWp[i] = inc - p;
        if (lane == 31) sGsum[g] = inc;
    }
    __syncthreads();

    // ---------------- Phase B: ranked writes from registers -----------------
    if (nib == 0u) return;

    const unsigned w = sBits[wi];
    const unsigned shift = (lane & 7) * 4;
    const int wordBase = sExcl + ((wi >= 32) ? sGsum[0] : 0) + sWp[wi];

    const float fbatch = (float)(bf / Ss);
    const float ftime  = (float)(bf % Ss);
    float* __restrict__ outFeat  = out;
    float* __restrict__ outCoord = out + FEAT_ELEMS;

    #pragma unroll
    for (int j = 0; j < PITER; ++j) {
        if (nib & (1u << j)) {
            const int rank = wordBase + __popc(w & ((1u << (shift + j)) - 1u));
            if (rank < MAXP) {
                const int rem = pix + j;
                const int y = rem / Ww;
                const int x = rem - y * Ww;
                float4 f0 = make_float4(f4get(v[0], j), f4get(v[1], j),
                                        f4get(v[2], j), f4get(v[3], j));
                float4 f1 = make_float4(f4get(v[4], j), f4get(v[5], j),
                                        f4get(v[6], j), f4get(v[7], j));
                ((float4*)outCoord)[rank] =
                    make_float4(fbatch, ftime, (float)y, (float)x);
                ((float4*)outFeat)[rank * 2 + 0] = f0;
                ((float4*)outFeat)[rank * 2 + 1] = f1;
            }
        }
    }
}

// ---------------------------------------------------------------------------
// Kernel 2: zero the tail [n_valid, MAXP) AND reset tile state for next call
// ---------------------------------------------------------------------------
__global__ void k_tail(float* __restrict__ out) {
    const int i = blockIdx.x * blockDim.x + threadIdx.x;
    if (i < NB) g_tile[i] = 0u;          // restore invariant for next replay
    int nv = g_total;
    if (nv > MAXP) nv = MAXP;
    if (i >= nv && i < MAXP) {
        const float4 z = make_float4(0.f, 0.f, 0.f, 0.f);
        ((float4*)(out + FEAT_ELEMS))[i] = z;
        ((float4*)out)[i * 2 + 0] = z;
        ((float4*)out)[i * 2 + 1] = z;
    }
}

// ---------------------------------------------------------------------------
extern "C" void kernel_launch(void* const* d_in, const int* in_sizes, int n_in,
                              void* d_out, int out_size) {
    const float* frames = (const float*)d_in[0];
    float* out = (float*)d_out;

    k_fused<<<NB, TPB>>>(frames, out);
    k_tail<<<(MAXP + 255) / 256, 256>>>(out);
}

// round 12
// speedup vs baseline: 1.0161x; 1.0161x over previous
#include <cuda_runtime.h>
#include <cuda_bf16.h>
#include <stdint.h>

// Problem geometry (fixed: frames (4,8,2,4,480,640) f32)
#define Ss 8
#define Cc 8
#define Hh 480
#define Ww 640
#define HW (Hh*Ww)               // 307200
#define NPIX (32*HW)             // 9,830,400
#define MAXP 200000
#define FEAT_ELEMS (MAXP*Cc)     // 1,600,000
#define THRESH 3.0f

// One block = one 1024-pixel chunk (307200/1024 = 300 -> never crosses a frame)
#define TPB 256
#define PITER 4                  // pixels per thread (one float4 per channel)
#define CHUNK (TPB*PITER)        // 1024
#define NB (NPIX/CHUNK)          // 9600
#define NWORDS (CHUNK/32)        // 32

// Decoupled-lookback tile state: bits[1:0] flag (0=invalid,1=partial,2=inclusive),
// bits[31:2] value. Zero at module load; k_tail re-zeroes after each call so the
// "all tiles invalid at entry" invariant holds for every graph replay.
__device__ unsigned g_tile[NB];
__device__ int g_total;

__device__ __forceinline__ float f4get(const float4& v, int j) {
    return j == 0 ? v.x : (j == 1 ? v.y : (j == 2 ? v.z : v.w));
}

// ---------------------------------------------------------------------------
// Fused mask + single-pass scan (decoupled lookback) + ranked register write
// ---------------------------------------------------------------------------
__global__ void __launch_bounds__(TPB, 3) k_fused(const float* __restrict__ frames,
                                                  float* __restrict__ out) {
    const int b    = blockIdx.x;
    const int tid  = threadIdx.x;
    const int lane = tid & 31;
    const int warp = tid >> 5;

    const long chunkStart = (long)b * CHUNK;
    const int bf   = (int)(chunkStart / HW);
    const int rem0 = (int)(chunkStart % HW);
    const float* __restrict__ base = frames + (size_t)bf * Cc * HW;

    __shared__ unsigned sBits[NWORDS];
    __shared__ int sWp[NWORDS];      // per-word exclusive prefix within block
    __shared__ int sWarp[TPB / 32];  // 8 per-warp counts
    __shared__ int sExcl;

    // ---------------- Phase A: load (features stay in registers) + mask -----
    const int pix = rem0 + tid * PITER;
    float4 v[Cc];
    #pragma unroll
    for (int c = 0; c < Cc; ++c)
        v[c] = __ldg((const float4*)(base + (size_t)c * HW + pix));

    float mx = 0.f, my = 0.f, mz = 0.f, mw = 0.f;
    #pragma unroll
    for (int c = 0; c < Cc; ++c) {
        mx = fmaxf(mx, fabsf(v[c].x));
        my = fmaxf(my, fabsf(v[c].y));
        mz = fmaxf(mz, fabsf(v[c].z));
        mw = fmaxf(mw, fabsf(v[c].w));
    }
    unsigned nib = (unsigned)(mx > THRESH)
                 | ((unsigned)(my > THRESH) << 1)
                 | ((unsigned)(mz > THRESH) << 2)
                 | ((unsigned)(mw > THRESH) << 3);
    unsigned word = nib << ((lane & 7) * 4);
    word |= __shfl_xor_sync(0xffffffffu, word, 1);
    word |= __shfl_xor_sync(0xffffffffu, word, 2);
    word |= __shfl_xor_sync(0xffffffffu, word, 4);

    int myPartial = 0;
    const int wi = warp * 4 + (lane >> 3);        // my bitmap word index (0..31)
    if ((lane & 7) == 0) {
        sBits[wi] = word;
        myPartial = __popc(word);
    }
    int warpSum = __reduce_add_sync(0xffffffffu, myPartial);
    if (lane == 0) sWarp[warp] = warpSum;
    __syncthreads();   // sBits + sWarp complete

    // ---------------- warp 0: publish + lookback; warp 1: word scan ---------
    if (warp == 0) {
        int vv = (lane < TPB / 32) ? sWarp[lane] : 0;
        int cnt = __reduce_add_sync(0xffffffffu, vv);

        if (lane == 0) {
            unsigned pub = ((unsigned)cnt << 2) | (b == 0 ? 2u : 1u);
            atomicExch(&g_tile[b], pub);
        }
        int excl = 0;
        if (b > 0) {
            int idx = b - 1;
            for (;;) {
                const int my_i = idx - lane;
                unsigned t = 2u;   // out-of-range: inclusive, value 0
                if (my_i >= 0) {
                    t = *((volatile unsigned*)&g_tile[my_i]);
                    while ((t & 3u) == 0u) {
                        __nanosleep(40);
                        t = *((volatile unsigned*)&g_tile[my_i]);
                    }
                }
                unsigned ball = __ballot_sync(0xffffffffu, (t & 3u) == 2u);
                if (ball) {
                    const int L = __ffs(ball) - 1;   // closest inclusive tile
                    int contrib = (lane <= L) ? (int)(t >> 2) : 0;
                    excl += __reduce_add_sync(0xffffffffu, contrib);
                    break;
                } else {
                    excl += __reduce_add_sync(0xffffffffu, (int)(t >> 2));
                    idx -= 32;
                }
            }
        }
        if (lane == 0) {
            sExcl = excl;
            if (b > 0) atomicExch(&g_tile[b], ((unsigned)(cnt + excl) << 2) | 2u);
            if (b == NB - 1) g_total = cnt + excl;
        }
    } else if (warp == 1) {
        // exclusive scan of the 32 word-popcounts
        int p = __popc(sBits[lane]);
        int inc = p;
        #pragma unroll
        for (int o = 1; o < 32; o <<= 1) {
            int s = __shfl_up_sync(0xffffffffu, inc, o);
            if (lane >= o) inc += s;
        }
        sWp[lane] = inc - p;
    }
    __syncthreads();

    // ---------------- Phase B: ranked writes from registers -----------------
    if (nib == 0u) return;

    const unsigned w = sBits[wi];
    const unsigned shift = (lane & 7) * 4;
    const int wordBase = sExcl + sWp[wi];

    const float fbatch = (float)(bf / Ss);
    const float ftime  = (float)(bf % Ss);
    float* __restrict__ outFeat  = out;
    float* __restrict__ outCoord = out + FEAT_ELEMS;

    #pragma unroll
    for (int j = 0; j < PITER; ++j) {
        if (nib & (1u << j)) {
            const int rank = wordBase + __popc(w & ((1u << (shift + j)) - 1u));
            if (rank < MAXP) {
                const int rem = pix + j;
                const int y = rem / Ww;
                const int x = rem - y * Ww;
                float4 f0 = make_float4(f4get(v[0], j), f4get(v[1], j),
                                        f4get(v[2], j), f4get(v[3], j));
                float4 f1 = make_float4(f4get(v[4], j), f4get(v[5], j),
                                        f4get(v[6], j), f4get(v[7], j));
                ((float4*)outCoord)[rank] =
                    make_float4(fbatch, ftime, (float)y, (float)x);
                ((float4*)outFeat)[rank * 2 + 0] = f0;
                ((float4*)outFeat)[rank * 2 + 1] = f1;
            }
        }
    }
}

// ---------------------------------------------------------------------------
// Tail: zero [n_valid, MAXP) AND reset tile state for the next replay
// ---------------------------------------------------------------------------
__global__ void k_tail(float* __restrict__ out) {
    const int i = blockIdx.x * blockDim.x + threadIdx.x;
    if (i < NB) g_tile[i] = 0u;          // restore invariant for next call
    int nv = g_total;
    if (nv > MAXP) nv = MAXP;
    if (i >= nv && i < MAXP) {
        const float4 z = make_float4(0.f, 0.f, 0.f, 0.f);
        ((float4*)(out + FEAT_ELEMS))[i] = z;
        ((float4*)out)[i * 2 + 0] = z;
        ((float4*)out)[i * 2 + 1] = z;
    }
}

// ---------------------------------------------------------------------------
extern "C" void kernel_launch(void* const* d_in, const int* in_sizes, int n_in,
                              void* d_out, int out_size) {
    const float* frames = (const float*)d_in[0];
    float* out = (float*)d_out;

    k_fused<<<NB, TPB>>>(frames, out);
    k_tail<<<(MAXP + 255) / 256, 256>>>(out);
}

// round 13
// speedup vs baseline: 1.1075x; 1.0900x over previous
#include <cuda_runtime.h>
#include <cuda_bf16.h>
#include <stdint.h>

// Problem geometry (fixed: frames (4,8,2,4,480,640) f32)
#define Ss 8
#define Cc 8
#define Hh 480
#define Ww 640
#define HW (Hh*Ww)               // 307200
#define NPIX (32*HW)             // 9,830,400
#define MAXP 200000
#define FEAT_ELEMS (MAXP*Cc)     // 1,600,000
#define THRESH 3.0f

// One block = one 2048-pixel chunk (307200/2048 = 150 -> never crosses a frame)
#define TPB 512
#define PITER 4                  // pixels per thread (one float4 per channel)
#define CHUNK (TPB*PITER)        // 2048
#define NB (NPIX/CHUNK)          // 4800
#define NWORDS (CHUNK/32)        // 64

// Decoupled-lookback tile state: bits[1:0] flag (0=invalid,1=partial,2=inclusive),
// bits[31:2] value. Zero at module load; the LAST-FINISHED block re-zeroes the
// state at the end of each call, so the invariant holds for every graph replay.
__device__ unsigned g_tile[NB];
__device__ int g_total;
__device__ int g_done;

// ---------------------------------------------------------------------------
// Single fused kernel: mask + single-pass scan + ranked write + tail cleanup
// ---------------------------------------------------------------------------
__global__ void __launch_bounds__(TPB) k_fused(const float* __restrict__ frames,
                                               float* __restrict__ out) {
    const int b    = blockIdx.x;
    const int tid  = threadIdx.x;
    const int lane = tid & 31;
    const int warp = tid >> 5;

    const long chunkStart = (long)b * CHUNK;
    const int bf   = (int)(chunkStart / HW);
    const int rem0 = (int)(chunkStart % HW);
    const float* __restrict__ base = frames + (size_t)bf * Cc * HW;

    __shared__ unsigned sBits[NWORDS];
    __shared__ int sWp[NWORDS];      // per-word exclusive prefix within 32-word group
    __shared__ int sGsum[2];         // group totals (2 groups of 32 words)
    __shared__ int sWarp[TPB / 32];
    __shared__ int sExcl;
    __shared__ int sLast;

    // ---------------- Phase A: stream + mask (features NOT held) ------------
    const int pix = rem0 + tid * PITER;
    float mx = 0.f, my = 0.f, mz = 0.f, mw = 0.f;
    #pragma unroll
    for (int c = 0; c < Cc; ++c) {
        float4 v = __ldg((const float4*)(base + (size_t)c * HW + pix));
        mx = fmaxf(mx, fabsf(v.x));
        my = fmaxf(my, fabsf(v.y));
        mz = fmaxf(mz, fabsf(v.z));
        mw = fmaxf(mw, fabsf(v.w));
    }
    const unsigned nib = (unsigned)(mx > THRESH)
                       | ((unsigned)(my > THRESH) << 1)
                       | ((unsigned)(mz > THRESH) << 2)
                       | ((unsigned)(mw > THRESH) << 3);
    unsigned word = nib << ((lane & 7) * 4);
    word |= __shfl_xor_sync(0xffffffffu, word, 1);
    word |= __shfl_xor_sync(0xffffffffu, word, 2);
    word |= __shfl_xor_sync(0xffffffffu, word, 4);

    int myPartial = 0;
    const int wi = warp * 4 + (lane >> 3);        // my bitmap word index (0..63)
    if ((lane & 7) == 0) {
        sBits[wi] = word;
        myPartial = __popc(word);
    }
    int warpSum = __reduce_add_sync(0xffffffffu, myPartial);
    if (lane == 0) sWarp[warp] = warpSum;
    __syncthreads();   // sBits + sWarp complete

    // ---------------- warp 0: publish + lookback; warps 1-2: word scan ------
    if (warp == 0) {
        int vv = (lane < TPB / 32) ? sWarp[lane] : 0;
        int cnt = __reduce_add_sync(0xffffffffu, vv);

        if (lane == 0) {
            unsigned pub = ((unsigned)cnt << 2) | (b == 0 ? 2u : 1u);
            atomicExch(&g_tile[b], pub);
        }
        int excl = 0;
        if (b > 0) {
            int idx = b - 1;
            for (;;) {
                const int my_i = idx - lane;
                unsigned t = 2u;   // out-of-range: inclusive, value 0
                if (my_i >= 0) {
                    t = *((volatile unsigned*)&g_tile[my_i]);
                    while ((t & 3u) == 0u) {
                        __nanosleep(40);
                        t = *((volatile unsigned*)&g_tile[my_i]);
                    }
                }
                unsigned ball = __ballot_sync(0xffffffffu, (t & 3u) == 2u);
                if (ball) {
                    const int L = __ffs(ball) - 1;   // closest inclusive tile
                    int contrib = (lane <= L) ? (int)(t >> 2) : 0;
                    excl += __reduce_add_sync(0xffffffffu, contrib);
                    break;
                } else {
                    excl += __reduce_add_sync(0xffffffffu, (int)(t >> 2));
                    idx -= 32;
                }
            }
        }
        if (lane == 0) {
            sExcl = excl;
            if (b > 0) atomicExch(&g_tile[b], ((unsigned)(cnt + excl) << 2) | 2u);
            if (b == NB - 1) g_total = cnt + excl;
        }
    } else if (warp <= 2) {
        // exclusive scan of the 64 word-popcounts (2 groups of 32)
        const int g = warp - 1;
        const int i = g * 32 + lane;
        int p = __popc(sBits[i]);
        int inc = p;
        #pragma unroll
        for (int o = 1; o < 32; o <<= 1) {
            int s = __shfl_up_sync(0xffffffffu, inc, o);
            if (lane >= o) inc += s;
        }
        sWp[i] = inc - p;
        if (lane == 31) sGsum[g] = inc;
    }
    __syncthreads();

    // ---------------- Phase B: ranked writes (gather hits L1) ---------------
    if (nib != 0u) {
        const unsigned w = sBits[wi];
        const unsigned shift = (lane & 7) * 4;
        const int wordBase = sExcl + ((wi >= 32) ? sGsum[0] : 0) + sWp[wi];

        const float fbatch = (float)(bf / Ss);
        const float ftime  = (float)(bf % Ss);
        float* __restrict__ outFeat  = out;
        float* __restrict__ outCoord = out + FEAT_ELEMS;

        #pragma unroll
        for (int j = 0; j < PITER; ++j) {
            if (nib & (1u << j)) {
                const int rank = wordBase + __popc(w & ((1u << (shift + j)) - 1u));
                if (rank < MAXP) {
                    const int rem = pix + j;
                    const int y = rem / Ww;
                    const int x = rem - y * Ww;
                    float4 f0, f1;
                    f0.x = __ldg(base + 0 * (size_t)HW + rem);
                    f0.y = __ldg(base + 1 * (size_t)HW + rem);
                    f0.z = __ldg(base + 2 * (size_t)HW + rem);
                    f0.w = __ldg(base + 3 * (size_t)HW + rem);
                    f1.x = __ldg(base + 4 * (size_t)HW + rem);
                    f1.y = __ldg(base + 5 * (size_t)HW + rem);
                    f1.z = __ldg(base + 6 * (size_t)HW + rem);
                    f1.w = __ldg(base + 7 * (size_t)HW + rem);
                    ((float4*)outCoord)[rank] =
                        make_float4(fbatch, ftime, (float)y, (float)x);
                    ((float4*)outFeat)[rank * 2 + 0] = f0;
                    ((float4*)outFeat)[rank * 2 + 1] = f1;
                }
            }
        }
    }

    // ---------------- Last-finished block: tail zero + state reset ----------
    if (tid == 0) {
        __threadfence();
        sLast = (atomicAdd(&g_done, 1) == NB - 1);
    }
    __syncthreads();
    if (sLast) {
        int nv = g_total;
        if (nv > MAXP) nv = MAXP;
        // zero output tail [nv, MAXP) -- no-op when hits >= MAXP
        const float4 z = make_float4(0.f, 0.f, 0.f, 0.f);
        for (int i = nv + tid; i < MAXP; i += TPB) {
            ((float4*)(out + FEAT_ELEMS))[i] = z;
            ((float4*)out)[i * 2 + 0] = z;
            ((float4*)out)[i * 2 + 1] = z;
        }
        // reset lookback state for the next graph replay
        for (int i = tid; i < NB; i += TPB) g_tile[i] = 0u;
        if (tid == 0) g_done = 0;
    }
}

// ---------------------------------------------------------------------------
extern "C" void kernel_launch(void* const* d_in, const int* in_sizes, int n_in,
                              void* d_out, int out_size) {
    const float* frames = (const float*)d_in[0];
    float* out = (float*)d_out;
    k_fused<<<NB, TPB>>>(frames, out);
}